// round 4
// baseline (speedup 1.0000x reference)
#include <cuda_runtime.h>
#include <cuda_bf16.h>
#include <cstdint>

// Problem constants (fixed by the dataset): B=2, N=250000, C=32, S=128
#define NPTS   250000
#define NBATCH 2
#define MTOT   (NPTS * NBATCH)        // 500000
#define CDIM   32
#define SDIM   128
#define GRID_CELLS (NBATCH * SDIM * SDIM * SDIM)  // 4,194,304

#define SLOTS    1536                 // grid slots scanned per gemm block
#define GTHREADS 384                  // threads per gemm block (12 warps)
#define GWARPS   (GTHREADS / 32)

// dynamic smem layout (floats/ints):
//   s_W  : 1024 floats                     (4096 B)
//   s_in : SLOTS ints                      (6144 B)
//   s_om : SLOTS ints                      (6144 B)
//   s_tr : GWARPS * 32*33 floats           (50688 B)
#define SMEM_W_OFF   0
#define SMEM_IN_OFF  (CDIM * CDIM)                  // in 4-byte words
#define SMEM_OM_OFF  (SMEM_IN_OFF + SLOTS)
#define SMEM_TR_OFF  (SMEM_OM_OFF + SLOTS)
#define SMEM_WORDS   (SMEM_TR_OFF + GWARPS * 32 * 33)
#define SMEM_BYTES   (SMEM_WORDS * 4)               // 67072 B

// Scratch (no cudaMalloc allowed): hash grid, neighbor table, intermediates
__device__ int   g_grid[GRID_CELLS];
__device__ int   g_nbr[27 * MTOT];           // 54 MB, built once, reused x3
__device__ float g_x1[MTOT * CDIM];
__device__ float g_x2[MTOT * CDIM];

typedef unsigned long long ull;

// ---------------------------------------------------------------------------
// packed f32x2 helpers (Blackwell dual-rate fp32)
// ---------------------------------------------------------------------------
__device__ __forceinline__ ull pack2(float lo, float hi) {
    ull r;
    asm("mov.b64 %0, {%1, %2};" : "=l"(r) : "f"(lo), "f"(hi));
    return r;
}
__device__ __forceinline__ void unpack2(ull v, float& lo, float& hi) {
    asm("mov.b64 {%0, %1}, %2;" : "=f"(lo), "=f"(hi) : "l"(v));
}
__device__ __forceinline__ void ffma2(ull& d, ull a, ull b) {
    asm("fma.rn.f32x2 %0, %1, %2, %0;" : "+l"(d) : "l"(a), "l"(b));
}

// ---------------------------------------------------------------------------
// init grid to -1
// ---------------------------------------------------------------------------
__global__ void init_grid_kernel() {
    int i = blockIdx.x * blockDim.x + threadIdx.x;
    if (i < GRID_CELLS / 4) {
        reinterpret_cast<int4*>(g_grid)[i] = make_int4(-1, -1, -1, -1);
    }
}

// ---------------------------------------------------------------------------
// scatter point index into grid
// ---------------------------------------------------------------------------
__global__ void scatter_kernel(const int* __restrict__ coords) {
    int m = blockIdx.x * blockDim.x + threadIdx.x;
    if (m >= MTOT) return;
    int b = (m >= NPTS) ? 1 : 0;
    int x = coords[3 * m + 0];
    int y = coords[3 * m + 1];
    int z = coords[3 * m + 2];
    g_grid[((b * SDIM + x) * SDIM + y) * SDIM + z] = m;
}

// ---------------------------------------------------------------------------
// build neighbor table: g_nbr[k][m] = input index at offset k, or -1
// ---------------------------------------------------------------------------
__global__ void build_nbr_kernel(const int* __restrict__ coords) {
    int m = blockIdx.x * blockDim.x + threadIdx.x;
    int k = blockIdx.y;
    if (m >= MTOT) return;
    int b = (m >= NPTS) ? 1 : 0;
    int dx = k / 9 - 1;
    int dy = (k / 3) % 3 - 1;
    int dz = k % 3 - 1;
    int nx = coords[3 * m + 0] + dx;
    int ny = coords[3 * m + 1] + dy;
    int nz = coords[3 * m + 2] + dz;
    int idx = -1;
    if ((unsigned)nx < SDIM && (unsigned)ny < SDIM && (unsigned)nz < SDIM)
        idx = g_grid[((b * SDIM + nx) * SDIM + ny) * SDIM + nz];
    g_nbr[k * MTOT + m] = idx;
}

// ---------------------------------------------------------------------------
// zero a float buffer (float4 stores)
// ---------------------------------------------------------------------------
__global__ void zero_kernel(float* __restrict__ p, int n4) {
    int i = blockIdx.x * blockDim.x + threadIdx.x;
    if (i < n4) reinterpret_cast<float4*>(p)[i] = make_float4(0.f, 0.f, 0.f, 0.f);
}

// ---------------------------------------------------------------------------
// gather-GEMM-scatter for one layer.
// grid: (ceil(MTOT/SLOTS), 27). Block: 384 threads = 12 warps.
// Block (cx, k): compacts valid (in,out) pairs from SLOTS slots of nbr[k],
// stages W[k] in smem, then each thread handles TWO pairs:
//   features streamed in 8-cin chunks with one-chunk LDG.128 prefetch,
//   W rows broadcast from smem (LDS.128) amortized over both pairs,
//   64 couts accumulated as 32 packed f32x2.
// Scatter: per-warp smem transpose, row-coalesced atomicAdd.
// ---------------------------------------------------------------------------
__global__ __launch_bounds__(GTHREADS, 1)
void spconv_gemm_kernel(const float* __restrict__ in,
                        float*       __restrict__ out,
                        const float* __restrict__ W,
                        int relu_in)
{
    extern __shared__ float smem[];
    float* s_W  = smem + SMEM_W_OFF;
    int*   s_in = reinterpret_cast<int*>(smem + SMEM_IN_OFF);
    int*   s_om = reinterpret_cast<int*>(smem + SMEM_OM_OFF);
    float* s_trb = smem + SMEM_TR_OFF;
    __shared__ int s_cnt;

    const int tid  = threadIdx.x;
    const int lane = tid & 31;
    const int wid  = tid >> 5;
    const int k    = blockIdx.y;
    const int base = blockIdx.x * SLOTS;

    if (tid == 0) s_cnt = 0;
    for (int i = tid; i < CDIM * CDIM; i += GTHREADS)
        s_W[i] = W[k * (CDIM * CDIM) + i];
    __syncthreads();

    // --- compact valid pairs (warp-aggregated) ---
    const int* nb = g_nbr + (long long)k * MTOT;
    #pragma unroll
    for (int it = 0; it < SLOTS / GTHREADS; ++it) {
        int s = it * GTHREADS + tid;
        int m = base + s;
        int v = (m < MTOT) ? __ldg(nb + m) : -1;
        unsigned bal = __ballot_sync(0xffffffffu, v >= 0);
        int cnt = __popc(bal);
        int bpos = 0;
        if (lane == 0 && cnt) bpos = atomicAdd(&s_cnt, cnt);
        bpos = __shfl_sync(0xffffffffu, bpos, 0);
        if (v >= 0) {
            int r = __popc(bal & ((1u << lane) - 1));
            s_in[bpos + r] = v;
            s_om[bpos + r] = m;
        }
    }
    __syncthreads();
    const int V = s_cnt;

    // --- GEMM over compacted pairs: each warp takes 64 pairs per iteration ---
    for (int g0 = wid * 64; g0 < V; g0 += GWARPS * 64) {
        const int pA = g0 + lane;
        const int pB = g0 + 32 + lane;
        const int iA = (pA < V) ? s_in[pA] : 0;
        const int iB = (pB < V) ? s_in[pB] : 0;
        const float4* fA = reinterpret_cast<const float4*>(in + iA * CDIM);
        const float4* fB = reinterpret_cast<const float4*>(in + iB * CDIM);

        // prefetch chunk 0 (cins 0..7) for both pairs
        float4 a0 = __ldg(fA + 0), a1 = __ldg(fA + 1);
        float4 b0 = __ldg(fB + 0), b1 = __ldg(fB + 1);

        ull accA[16], accB[16];
        #pragma unroll
        for (int i = 0; i < 16; i++) { accA[i] = 0ull; accB[i] = 0ull; }

        #pragma unroll
        for (int ch = 0; ch < 4; ch++) {
            float4 na0, na1, nb0, nb1;
            if (ch < 3) {                           // prefetch next chunk
                na0 = __ldg(fA + 2 * ch + 2); na1 = __ldg(fA + 2 * ch + 3);
                nb0 = __ldg(fB + 2 * ch + 2); nb1 = __ldg(fB + 2 * ch + 3);
            }
            float ra[8] = {a0.x, a0.y, a0.z, a0.w, a1.x, a1.y, a1.z, a1.w};
            float rb[8] = {b0.x, b0.y, b0.z, b0.w, b1.x, b1.y, b1.z, b1.w};
            if (relu_in) {
                #pragma unroll
                for (int j = 0; j < 8; j++) {
                    ra[j] = fmaxf(ra[j], 0.f);
                    rb[j] = fmaxf(rb[j], 0.f);
                }
            }
            #pragma unroll
            for (int j = 0; j < 8; j++) {
                const int c = ch * 8 + j;
                const ull fa = pack2(ra[j], ra[j]);
                const ull fb = pack2(rb[j], rb[j]);
                const ulonglong2* wr =
                    reinterpret_cast<const ulonglong2*>(s_W + c * CDIM);
                #pragma unroll
                for (int t = 0; t < 8; t++) {
                    ulonglong2 q = wr[t];           // LDS.128 broadcast
                    ffma2(accA[2 * t + 0], fa, q.x);
                    ffma2(accA[2 * t + 1], fa, q.y);
                    ffma2(accB[2 * t + 0], fb, q.x);
                    ffma2(accB[2 * t + 1], fb, q.y);
                }
            }
            a0 = na0; a1 = na1; b0 = nb0; b1 = nb1;
        }

        float* tp = s_trb + wid * (32 * 33);

        // --- scatter group A (pairs g0..g0+31) ---
        {
            #pragma unroll
            for (int i = 0; i < 16; i++) {
                float lo, hi;
                unpack2(accA[i], lo, hi);
                tp[(2 * i + 0) * 33 + lane] = lo;
                tp[(2 * i + 1) * 33 + lane] = hi;
            }
            __syncwarp();
            const int nv = min(32, V - g0);
            for (int j = 0; j < nv; j++) {
                int mo = s_om[g0 + j];
                atomicAdd(out + mo * CDIM + lane, tp[lane * 33 + j]);
            }
            __syncwarp();
        }
        // --- scatter group B (pairs g0+32..g0+63) ---
        if (V > g0 + 32) {
            #pragma unroll
            for (int i = 0; i < 16; i++) {
                float lo, hi;
                unpack2(accB[i], lo, hi);
                tp[(2 * i + 0) * 33 + lane] = lo;
                tp[(2 * i + 1) * 33 + lane] = hi;
            }
            __syncwarp();
            const int nv = min(32, V - (g0 + 32));
            for (int j = 0; j < nv; j++) {
                int mo = s_om[g0 + 32 + j];
                atomicAdd(out + mo * CDIM + lane, tp[lane * 33 + j]);
            }
            __syncwarp();
        }
    }
}

// ---------------------------------------------------------------------------
// launch
// ---------------------------------------------------------------------------
extern "C" void kernel_launch(void* const* d_in, const int* in_sizes, int n_in,
                              void* d_out, int out_size)
{
    const float* features = nullptr;
    const int*   coords   = nullptr;
    const float* Ws[3]    = {nullptr, nullptr, nullptr};
    int wcount = 0;

    for (int i = 0; i < n_in; ++i) {
        if (in_sizes[i] == MTOT * CDIM && features == nullptr) {
            features = (const float*)d_in[i];
        } else if (in_sizes[i] == MTOT * 3 && coords == nullptr) {
            coords = (const int*)d_in[i];
        } else if (in_sizes[i] == 27 * CDIM * CDIM && wcount < 3) {
            Ws[wcount++] = (const float*)d_in[i];
        }
    }

    float* x1 = nullptr;
    float* x2 = nullptr;
    cudaGetSymbolAddress((void**)&x1, g_x1);
    cudaGetSymbolAddress((void**)&x2, g_x2);
    float* out = (float*)d_out;

    // opt in to >48KB dynamic smem (host-side attribute, capture-safe)
    cudaFuncSetAttribute(spconv_gemm_kernel,
                         cudaFuncAttributeMaxDynamicSharedMemorySize,
                         SMEM_BYTES);

    // 1) grid init + scatter + neighbor table (shared across all 3 layers)
    init_grid_kernel<<<(GRID_CELLS / 4 + 255) / 256, 256>>>();
    scatter_kernel<<<(MTOT + 255) / 256, 256>>>(coords);
    {
        dim3 g((MTOT + 255) / 256, 27);
        build_nbr_kernel<<<g, 256>>>(coords);
    }

    // 2) zero accumulation buffers (d_out is poisoned by the harness)
    const int n4 = MTOT * CDIM / 4;
    zero_kernel<<<(n4 + 255) / 256, 256>>>(x1, n4);
    zero_kernel<<<(n4 + 255) / 256, 256>>>(x2, n4);
    zero_kernel<<<(n4 + 255) / 256, 256>>>(out, n4);

    // 3) three layers of gather-GEMM-scatter
    dim3 gg((MTOT + SLOTS - 1) / SLOTS, 27);
    spconv_gemm_kernel<<<gg, GTHREADS, SMEM_BYTES>>>(features, x1, Ws[0], 0);
    spconv_gemm_kernel<<<gg, GTHREADS, SMEM_BYTES>>>(x1,       x2, Ws[1], 1);
    spconv_gemm_kernel<<<gg, GTHREADS, SMEM_BYTES>>>(x2,      out, Ws[2], 1);
}

// round 6
// speedup vs baseline: 1.0202x; 1.0202x over previous
#include <cuda_runtime.h>
#include <cuda_bf16.h>
#include <cstdint>

// Problem constants (fixed by the dataset): B=2, N=250000, C=32, S=128
#define NPTS   250000
#define NBATCH 2
#define MTOT   (NPTS * NBATCH)        // 500000
#define CDIM   32
#define SDIM   128
#define GRID_CELLS (NBATCH * SDIM * SDIM * SDIM)  // 4,194,304

#define SLOTS    1536                 // grid slots scanned per gemm block
#define GTHREADS 384                  // threads per gemm block (12 warps)
#define GWARPS   (GTHREADS / 32)

// dynamic smem layout (4-byte words):
//   s_W  : 1024 floats   s_in/s_om: SLOTS ints each   s_tr: GWARPS*32*33
#define SMEM_W_OFF   0
#define SMEM_IN_OFF  (CDIM * CDIM)
#define SMEM_OM_OFF  (SMEM_IN_OFF + SLOTS)
#define SMEM_TR_OFF  (SMEM_OM_OFF + SLOTS)
#define SMEM_WORDS   (SMEM_TR_OFF + GWARPS * 32 * 33)
#define SMEM_BYTES   (SMEM_WORDS * 4)               // 67072 B

// Scratch (no cudaMalloc allowed)
__device__ int   g_grid[GRID_CELLS];
__device__ int   g_nbr[27 * MTOT];           // built once, reused x3
__device__ float g_x1[MTOT * CDIM];
__device__ float g_x2[MTOT * CDIM];

typedef unsigned long long ull;

// ---------------------------------------------------------------------------
// packed f32x2 helpers (dual-rate fp32)
// ---------------------------------------------------------------------------
__device__ __forceinline__ ull pack2(float lo, float hi) {
    ull r;
    asm("mov.b64 %0, {%1, %2};" : "=l"(r) : "f"(lo), "f"(hi));
    return r;
}
__device__ __forceinline__ void unpack2(ull v, float& lo, float& hi) {
    asm("mov.b64 {%0, %1}, %2;" : "=f"(lo), "=f"(hi) : "l"(v));
}
__device__ __forceinline__ void ffma2(ull& d, ull a, ull b) {
    asm("fma.rn.f32x2 %0, %1, %2, %0;" : "+l"(d) : "l"(a), "l"(b));
}

// ---------------------------------------------------------------------------
// prepass kernels
// ---------------------------------------------------------------------------
__global__ void init_grid_kernel() {
    int i = blockIdx.x * blockDim.x + threadIdx.x;
    if (i < GRID_CELLS / 4)
        reinterpret_cast<int4*>(g_grid)[i] = make_int4(-1, -1, -1, -1);
}

__global__ void scatter_kernel(const int* __restrict__ coords) {
    int m = blockIdx.x * blockDim.x + threadIdx.x;
    if (m >= MTOT) return;
    int b = (m >= NPTS) ? 1 : 0;
    int x = coords[3 * m + 0];
    int y = coords[3 * m + 1];
    int z = coords[3 * m + 2];
    g_grid[((b * SDIM + x) * SDIM + y) * SDIM + z] = m;
}

__global__ void build_nbr_kernel(const int* __restrict__ coords) {
    int m = blockIdx.x * blockDim.x + threadIdx.x;
    int k = blockIdx.y;
    if (m >= MTOT) return;
    int b = (m >= NPTS) ? 1 : 0;
    int dx = k / 9 - 1;
    int dy = (k / 3) % 3 - 1;
    int dz = k % 3 - 1;
    int nx = coords[3 * m + 0] + dx;
    int ny = coords[3 * m + 1] + dy;
    int nz = coords[3 * m + 2] + dz;
    int idx = -1;
    if ((unsigned)nx < SDIM && (unsigned)ny < SDIM && (unsigned)nz < SDIM)
        idx = g_grid[((b * SDIM + nx) * SDIM + ny) * SDIM + nz];
    g_nbr[k * MTOT + m] = idx;
}

// fused zeroing of all three accumulation buffers (single launch)
__global__ void zero_all_kernel(float* __restrict__ a,
                                float* __restrict__ b,
                                float* __restrict__ c, int n4) {
    int i = blockIdx.x * blockDim.x + threadIdx.x;
    const float4 z = make_float4(0.f, 0.f, 0.f, 0.f);
    if (i < n4) {
        reinterpret_cast<float4*>(a)[i] = z;
        reinterpret_cast<float4*>(b)[i] = z;
        reinterpret_cast<float4*>(c)[i] = z;
    }
}

// ---------------------------------------------------------------------------
// gather-GEMM-scatter for one layer.
// grid: (ceil(MTOT/SLOTS), 27). Block: 384 threads = 12 warps.
// Each thread handles TWO pairs; features loaded in 8-cin chunks (no
// double-buffer -> ~120 regs, no spills); W rows broadcast from smem
// (LDS.128), amortized over both FMA streams; 64 couts as 32 packed f32x2.
// Scatter: per-warp smem transpose, row-coalesced atomicAdd.
// ---------------------------------------------------------------------------
__global__ __launch_bounds__(GTHREADS, 1)
void spconv_gemm_kernel(const float* __restrict__ in,
                        float*       __restrict__ out,
                        const float* __restrict__ W,
                        int relu_in)
{
    extern __shared__ float smem[];
    float* s_W   = smem + SMEM_W_OFF;
    int*   s_in  = reinterpret_cast<int*>(smem + SMEM_IN_OFF);
    int*   s_om  = reinterpret_cast<int*>(smem + SMEM_OM_OFF);
    float* s_trb = smem + SMEM_TR_OFF;
    __shared__ int s_cnt;

    const int tid  = threadIdx.x;
    const int lane = tid & 31;
    const int wid  = tid >> 5;
    const int k    = blockIdx.y;
    const int base = blockIdx.x * SLOTS;

    if (tid == 0) s_cnt = 0;
    for (int i = tid; i < CDIM * CDIM; i += GTHREADS)
        s_W[i] = W[k * (CDIM * CDIM) + i];
    __syncthreads();

    // --- compact valid pairs (warp-aggregated) ---
    const int* nb = g_nbr + (long long)k * MTOT;
    #pragma unroll
    for (int it = 0; it < SLOTS / GTHREADS; ++it) {
        int s = it * GTHREADS + tid;
        int m = base + s;
        int v = (m < MTOT) ? __ldg(nb + m) : -1;
        unsigned bal = __ballot_sync(0xffffffffu, v >= 0);
        int cnt = __popc(bal);
        int bpos = 0;
        if (lane == 0 && cnt) bpos = atomicAdd(&s_cnt, cnt);
        bpos = __shfl_sync(0xffffffffu, bpos, 0);
        if (v >= 0) {
            int r = __popc(bal & ((1u << lane) - 1));
            s_in[bpos + r] = v;
            s_om[bpos + r] = m;
        }
    }
    __syncthreads();
    const int V = s_cnt;

    // --- GEMM: each warp takes 64 pairs per iteration (2 per thread) ---
    for (int g0 = wid * 64; g0 < V; g0 += GWARPS * 64) {
        const int pA = g0 + lane;
        const int pB = g0 + 32 + lane;
        const int iA = (pA < V) ? s_in[pA] : 0;
        const int iB = (pB < V) ? s_in[pB] : 0;
        const float4* fA = reinterpret_cast<const float4*>(in + iA * CDIM);
        const float4* fB = reinterpret_cast<const float4*>(in + iB * CDIM);

        ull accA[16], accB[16];
        #pragma unroll
        for (int i = 0; i < 16; i++) { accA[i] = 0ull; accB[i] = 0ull; }

        #pragma unroll
        for (int ch = 0; ch < 4; ch++) {
            float4 a0 = __ldg(fA + 2 * ch), a1 = __ldg(fA + 2 * ch + 1);
            float4 b0 = __ldg(fB + 2 * ch), b1 = __ldg(fB + 2 * ch + 1);
            float ra[8] = {a0.x, a0.y, a0.z, a0.w, a1.x, a1.y, a1.z, a1.w};
            float rb[8] = {b0.x, b0.y, b0.z, b0.w, b1.x, b1.y, b1.z, b1.w};
            if (relu_in) {
                #pragma unroll
                for (int j = 0; j < 8; j++) {
                    ra[j] = fmaxf(ra[j], 0.f);
                    rb[j] = fmaxf(rb[j], 0.f);
                }
            }
            #pragma unroll
            for (int j = 0; j < 8; j++) {
                const int c = ch * 8 + j;
                const ull fa = pack2(ra[j], ra[j]);
                const ull fb = pack2(rb[j], rb[j]);
                const ulonglong2* wr =
                    reinterpret_cast<const ulonglong2*>(s_W + c * CDIM);
                #pragma unroll
                for (int t = 0; t < 8; t++) {
                    ulonglong2 q = wr[t];           // LDS.128 broadcast
                    ffma2(accA[2 * t + 0], fa, q.x);
                    ffma2(accA[2 * t + 1], fa, q.y);
                    ffma2(accB[2 * t + 0], fb, q.x);
                    ffma2(accB[2 * t + 1], fb, q.y);
                }
            }
        }

        float* tp = s_trb + wid * (32 * 33);

        // --- scatter group A (pairs g0..g0+31) ---
        {
            #pragma unroll
            for (int i = 0; i < 16; i++) {
                float lo, hi;
                unpack2(accA[i], lo, hi);
                tp[(2 * i + 0) * 33 + lane] = lo;
                tp[(2 * i + 1) * 33 + lane] = hi;
            }
            __syncwarp();
            const int nv = min(32, V - g0);
            for (int j = 0; j < nv; j++) {
                int mo = s_om[g0 + j];
                atomicAdd(out + mo * CDIM + lane, tp[lane * 33 + j]);
            }
            __syncwarp();
        }
        // --- scatter group B (pairs g0+32..g0+63) ---
        if (V > g0 + 32) {
            #pragma unroll
            for (int i = 0; i < 16; i++) {
                float lo, hi;
                unpack2(accB[i], lo, hi);
                tp[(2 * i + 0) * 33 + lane] = lo;
                tp[(2 * i + 1) * 33 + lane] = hi;
            }
            __syncwarp();
            const int nv = min(32, V - (g0 + 32));
            for (int j = 0; j < nv; j++) {
                int mo = s_om[g0 + 32 + j];
                atomicAdd(out + mo * CDIM + lane, tp[lane * 33 + j]);
            }
            __syncwarp();
        }
    }
}

// ---------------------------------------------------------------------------
// launch.  Order matters for ncu (-s 5 -c 1): launches are
// 1 init, 2 scatter, 3 build_nbr, 4 zero_all, 5 gemm1, 6 gemm2 <- profiled.
// ---------------------------------------------------------------------------
extern "C" void kernel_launch(void* const* d_in, const int* in_sizes, int n_in,
                              void* d_out, int out_size)
{
    const float* features = nullptr;
    const int*   coords   = nullptr;
    const float* Ws[3]    = {nullptr, nullptr, nullptr};
    int wcount = 0;

    for (int i = 0; i < n_in; ++i) {
        if (in_sizes[i] == MTOT * CDIM && features == nullptr) {
            features = (const float*)d_in[i];
        } else if (in_sizes[i] == MTOT * 3 && coords == nullptr) {
            coords = (const int*)d_in[i];
        } else if (in_sizes[i] == 27 * CDIM * CDIM && wcount < 3) {
            Ws[wcount++] = (const float*)d_in[i];
        }
    }

    float* x1 = nullptr;
    float* x2 = nullptr;
    cudaGetSymbolAddress((void**)&x1, g_x1);
    cudaGetSymbolAddress((void**)&x2, g_x2);
    float* out = (float*)d_out;

    cudaFuncSetAttribute(spconv_gemm_kernel,
                         cudaFuncAttributeMaxDynamicSharedMemorySize,
                         SMEM_BYTES);

    // 1) grid init + scatter + neighbor table (shared by all 3 layers)
    init_grid_kernel<<<(GRID_CELLS / 4 + 255) / 256, 256>>>();
    scatter_kernel<<<(MTOT + 255) / 256, 256>>>(coords);
    {
        dim3 g((MTOT + 255) / 256, 27);
        build_nbr_kernel<<<g, 256>>>(coords);
    }

    // 2) zero all accumulation buffers in one launch
    const int n4 = MTOT * CDIM / 4;
    zero_all_kernel<<<(n4 + 255) / 256, 256>>>(x1, x2, out, n4);

    // 3) three layers of gather-GEMM-scatter
    dim3 gg((MTOT + SLOTS - 1) / SLOTS, 27);
    spconv_gemm_kernel<<<gg, GTHREADS, SMEM_BYTES>>>(features, x1, Ws[0], 0);
    spconv_gemm_kernel<<<gg, GTHREADS, SMEM_BYTES>>>(x1,       x2, Ws[1], 1);
    spconv_gemm_kernel<<<gg, GTHREADS, SMEM_BYTES>>>(x2,      out, Ws[2], 1);
}

// round 7
// speedup vs baseline: 1.5281x; 1.4978x over previous
#include <cuda_runtime.h>
#include <cuda_bf16.h>
#include <cstdint>

// Problem constants (fixed by the dataset): B=2, N=250000, C=32, S=128
#define NPTS   250000
#define NBATCH 2
#define MTOT   (NPTS * NBATCH)        // 500000
#define CDIM   32
#define SDIM   128
#define GRID_CELLS (NBATCH * SDIM * SDIM * SDIM)  // 4,194,304

#define CHUNK    1024                 // output points per rulebook chunk
#define CHUNKS   ((MTOT + CHUNK - 1) / CHUNK)     // 489
#define GTHREADS 256                  // gemm block: 8 warps
#define GWARPS   (GTHREADS / 32)

// Scratch (no cudaMalloc allowed)
__device__ int   g_grid[GRID_CELLS];
__device__ int   g_cnt[27 * CHUNKS];              // valid pairs per (k,chunk)
__device__ int2  g_pairs[27 * CHUNKS * CHUNK];    // compacted (in_idx, out_m)
__device__ float g_x1[MTOT * CDIM];
__device__ float g_x2[MTOT * CDIM];

typedef unsigned long long ull;

// ---------------------------------------------------------------------------
// packed f32x2 helpers (dual-rate fp32)
// ---------------------------------------------------------------------------
__device__ __forceinline__ ull pack2(float lo, float hi) {
    ull r;
    asm("mov.b64 %0, {%1, %2};" : "=l"(r) : "f"(lo), "f"(hi));
    return r;
}
__device__ __forceinline__ void unpack2(ull v, float& lo, float& hi) {
    asm("mov.b64 {%0, %1}, %2;" : "=f"(lo), "=f"(hi) : "l"(v));
}
__device__ __forceinline__ void ffma2(ull& d, ull a, ull b) {
    asm("fma.rn.f32x2 %0, %1, %2, %0;" : "+l"(d) : "l"(a), "l"(b));
}

// ---------------------------------------------------------------------------
// fused prepass: grid init to -1 + zero all three accumulation buffers
// ---------------------------------------------------------------------------
__global__ void init_zero_kernel(float* __restrict__ a,
                                 float* __restrict__ b,
                                 float* __restrict__ c) {
    int i = blockIdx.x * blockDim.x + threadIdx.x;
    if (i < GRID_CELLS / 4)
        reinterpret_cast<int4*>(g_grid)[i] = make_int4(-1, -1, -1, -1);
    const int n4 = MTOT * CDIM / 4;
    const float4 z = make_float4(0.f, 0.f, 0.f, 0.f);
    if (i < n4) {
        reinterpret_cast<float4*>(a)[i] = z;
        reinterpret_cast<float4*>(b)[i] = z;
        reinterpret_cast<float4*>(c)[i] = z;
    }
}

// ---------------------------------------------------------------------------
// scatter point index into grid
// ---------------------------------------------------------------------------
__global__ void scatter_kernel(const int* __restrict__ coords) {
    int m = blockIdx.x * blockDim.x + threadIdx.x;
    if (m >= MTOT) return;
    int b = (m >= NPTS) ? 1 : 0;
    int x = coords[3 * m + 0];
    int y = coords[3 * m + 1];
    int z = coords[3 * m + 2];
    g_grid[((b * SDIM + x) * SDIM + y) * SDIM + z] = m;
}

// ---------------------------------------------------------------------------
// build compacted rulebook: for (k, chunk) write valid (in_idx, out_m)
// pairs contiguously + count.  grid: (CHUNKS, 27), block 256.
// ---------------------------------------------------------------------------
__global__ void build_rules_kernel(const int* __restrict__ coords) {
    __shared__ int s_cnt;
    const int tid  = threadIdx.x;
    const int lane = tid & 31;
    const int k    = blockIdx.y;
    const int base = blockIdx.x * CHUNK;

    if (tid == 0) s_cnt = 0;
    __syncthreads();

    const int dx = k / 9 - 1;
    const int dy = (k / 3) % 3 - 1;
    const int dz = k % 3 - 1;
    int2* pout = g_pairs + (k * CHUNKS + blockIdx.x) * CHUNK;

    #pragma unroll
    for (int it = 0; it < CHUNK / 256; ++it) {
        const int m = base + it * 256 + tid;
        int idx = -1;
        if (m < MTOT) {
            const int b  = (m >= NPTS) ? 1 : 0;
            const int nx = coords[3 * m + 0] + dx;
            const int ny = coords[3 * m + 1] + dy;
            const int nz = coords[3 * m + 2] + dz;
            if ((unsigned)nx < SDIM && (unsigned)ny < SDIM && (unsigned)nz < SDIM)
                idx = __ldg(g_grid + ((b * SDIM + nx) * SDIM + ny) * SDIM + nz);
        }
        unsigned bal = __ballot_sync(0xffffffffu, idx >= 0);
        int cnt = __popc(bal);
        int bpos = 0;
        if (lane == 0 && cnt) bpos = atomicAdd(&s_cnt, cnt);
        bpos = __shfl_sync(0xffffffffu, bpos, 0);
        if (idx >= 0) {
            int r = __popc(bal & ((1u << lane) - 1));
            pout[bpos + r] = make_int2(idx, m);
        }
    }
    __syncthreads();
    if (tid == 0) g_cnt[k * CHUNKS + blockIdx.x] = s_cnt;
}

// ---------------------------------------------------------------------------
// gather-GEMM-scatter for one layer (R2 core, compaction precomputed).
// grid: (CHUNKS, 27). Block 256 = 8 warps. Thread-per-pair:
//   gather own 32-float feature row (8x LDG.128, optional ReLU),
//   W rows broadcast from smem (LDS.128), 32 couts as 16 packed f32x2,
//   per-warp smem transpose, row-coalesced atomicAdd scatter.
// Out-index for scatter comes from __shfl of the pair register.
// ---------------------------------------------------------------------------
__global__ __launch_bounds__(GTHREADS)
void spconv_gemm_kernel(const float* __restrict__ in,
                        float*       __restrict__ out,
                        const float* __restrict__ W,
                        int relu_in)
{
    __shared__ float s_W[CDIM * CDIM];           // 4 KB
    __shared__ float s_tr[GWARPS][32 * 33];      // 33.8 KB

    const int k = blockIdx.y;
    const int c = blockIdx.x;
    const int V = __ldg(g_cnt + k * CHUNKS + c);
    if (V == 0) return;

    const int tid  = threadIdx.x;
    const int lane = tid & 31;
    const int wid  = tid >> 5;

    for (int i = tid; i < CDIM * CDIM; i += GTHREADS)
        s_W[i] = W[k * (CDIM * CDIM) + i];
    __syncthreads();

    const int2* pairs = g_pairs + (k * CHUNKS + c) * CHUNK;

    for (int g0 = wid * 32; g0 < V; g0 += GWARPS * 32) {
        const int p = g0 + lane;
        const int2 pr = (p < V) ? __ldg(pairs + p) : make_int2(0, 0);

        // gather this pair's feature row (32 floats)
        const float4* fp = reinterpret_cast<const float4*>(in + pr.x * CDIM);
        float fr[32];
        #pragma unroll
        for (int j = 0; j < 8; j++) {
            float4 q = __ldg(fp + j);
            if (relu_in) {
                q.x = fmaxf(q.x, 0.f); q.y = fmaxf(q.y, 0.f);
                q.z = fmaxf(q.z, 0.f); q.w = fmaxf(q.w, 0.f);
            }
            fr[4 * j + 0] = q.x; fr[4 * j + 1] = q.y;
            fr[4 * j + 2] = q.z; fr[4 * j + 3] = q.w;
        }

        ull acc[16];
        #pragma unroll
        for (int i = 0; i < 16; i++) acc[i] = 0ull;

        #pragma unroll
        for (int cin = 0; cin < 32; cin++) {
            const ull fv = pack2(fr[cin], fr[cin]);
            const ulonglong2* wr =
                reinterpret_cast<const ulonglong2*>(s_W + cin * CDIM);
            #pragma unroll
            for (int t = 0; t < 8; t++) {
                ulonglong2 q = wr[t];                // LDS.128 broadcast
                ffma2(acc[2 * t + 0], fv, q.x);
                ffma2(acc[2 * t + 1], fv, q.y);
            }
        }

        // transpose: tp[cout][pair_lane]
        float* tp = s_tr[wid];
        #pragma unroll
        for (int i = 0; i < 16; i++) {
            float lo, hi;
            unpack2(acc[i], lo, hi);
            tp[(2 * i + 0) * 33 + lane] = lo;
            tp[(2 * i + 1) * 33 + lane] = hi;
        }
        __syncwarp();

        // scatter: lanes = couts of one pair row, coalesced 128B atomics
        const int nv = min(32, V - g0);
        for (int j = 0; j < nv; j++) {
            const int mo = __shfl_sync(0xffffffffu, pr.y, j);
            atomicAdd(out + mo * CDIM + lane, tp[lane * 33 + j]);
        }
        __syncwarp();
    }
}

// ---------------------------------------------------------------------------
// launch.  Positions: init_zero(1), scatter(2), build_rules(3),
// gemm1(4), gemm2(5), gemm3(6)  ->  ncu lands on a gemm either way.
// ---------------------------------------------------------------------------
extern "C" void kernel_launch(void* const* d_in, const int* in_sizes, int n_in,
                              void* d_out, int out_size)
{
    const float* features = nullptr;
    const int*   coords   = nullptr;
    const float* Ws[3]    = {nullptr, nullptr, nullptr};
    int wcount = 0;

    for (int i = 0; i < n_in; ++i) {
        if (in_sizes[i] == MTOT * CDIM && features == nullptr) {
            features = (const float*)d_in[i];
        } else if (in_sizes[i] == MTOT * 3 && coords == nullptr) {
            coords = (const int*)d_in[i];
        } else if (in_sizes[i] == 27 * CDIM * CDIM && wcount < 3) {
            Ws[wcount++] = (const float*)d_in[i];
        }
    }

    float* x1 = nullptr;
    float* x2 = nullptr;
    cudaGetSymbolAddress((void**)&x1, g_x1);
    cudaGetSymbolAddress((void**)&x2, g_x2);
    float* out = (float*)d_out;

    // 1) fused grid-init + zero of all accumulation buffers
    {
        const int n = MTOT * CDIM / 4;    // > GRID_CELLS/4
        init_zero_kernel<<<(n + 255) / 256, 256>>>(x1, x2, out);
    }
    // 2) scatter
    scatter_kernel<<<(MTOT + 255) / 256, 256>>>(coords);
    // 3) compacted rulebook (shared by all 3 layers)
    {
        dim3 g(CHUNKS, 27);
        build_rules_kernel<<<g, 256>>>(coords);
    }
    // 4-6) three layers of gather-GEMM-scatter
    {
        dim3 g(CHUNKS, 27);
        spconv_gemm_kernel<<<g, GTHREADS>>>(features, x1, Ws[0], 0);
        spconv_gemm_kernel<<<g, GTHREADS>>>(x1,       x2, Ws[1], 1);
        spconv_gemm_kernel<<<g, GTHREADS>>>(x2,      out, Ws[2], 1);
    }
}

// round 9
// speedup vs baseline: 1.6047x; 1.0501x over previous
#include <cuda_runtime.h>
#include <cuda_bf16.h>
#include <cstdint>

// Problem constants (fixed by the dataset): B=2, N=250000, C=32, S=128
#define NPTS   250000
#define NBATCH 2
#define MTOT   (NPTS * NBATCH)        // 500000
#define CDIM   32
#define SDIM   128
#define GRID_CELLS (NBATCH * SDIM * SDIM * SDIM)  // 4,194,304

#define CHUNK    1024                 // output points per rulebook chunk
#define CHUNKS   ((MTOT + CHUNK - 1) / CHUNK)     // 489
#define GTHREADS 256                  // gemm block: 8 warps
#define GWARPS   (GTHREADS / 32)
#define TSTRIDE  36                   // tile row stride (mult of 4: 16B align)

// Scratch (no cudaMalloc allowed)
__device__ int   g_grid[GRID_CELLS];
__device__ int   g_cnt[27 * CHUNKS];              // valid pairs per (k,chunk)
__device__ int2  g_pairs[27 * CHUNKS * CHUNK];    // compacted (in_idx, out_m)
__device__ float g_x1[MTOT * CDIM];
__device__ float g_x2[MTOT * CDIM];

typedef unsigned long long ull;

// ---------------------------------------------------------------------------
// packed f32x2 helpers (dual-rate fp32)
// ---------------------------------------------------------------------------
__device__ __forceinline__ ull pack2(float lo, float hi) {
    ull r;
    asm("mov.b64 %0, {%1, %2};" : "=l"(r) : "f"(lo), "f"(hi));
    return r;
}
__device__ __forceinline__ void ffma2(ull& d, ull a, ull b) {
    asm("fma.rn.f32x2 %0, %1, %2, %0;" : "+l"(d) : "l"(a), "l"(b));
}

// ---------------------------------------------------------------------------
// fused prepass: grid init to -1 + zero all three accumulation buffers
// ---------------------------------------------------------------------------
__global__ void init_zero_kernel(float* __restrict__ a,
                                 float* __restrict__ b,
                                 float* __restrict__ c) {
    int i = blockIdx.x * blockDim.x + threadIdx.x;
    if (i < GRID_CELLS / 4)
        reinterpret_cast<int4*>(g_grid)[i] = make_int4(-1, -1, -1, -1);
    const int n4 = MTOT * CDIM / 4;
    const float4 z = make_float4(0.f, 0.f, 0.f, 0.f);
    if (i < n4) {
        reinterpret_cast<float4*>(a)[i] = z;
        reinterpret_cast<float4*>(b)[i] = z;
        reinterpret_cast<float4*>(c)[i] = z;
    }
}

// ---------------------------------------------------------------------------
// scatter point index into grid
// ---------------------------------------------------------------------------
__global__ void scatter_kernel(const int* __restrict__ coords) {
    int m = blockIdx.x * blockDim.x + threadIdx.x;
    if (m >= MTOT) return;
    int b = (m >= NPTS) ? 1 : 0;
    int x = coords[3 * m + 0];
    int y = coords[3 * m + 1];
    int z = coords[3 * m + 2];
    g_grid[((b * SDIM + x) * SDIM + y) * SDIM + z] = m;
}

// ---------------------------------------------------------------------------
// build compacted rulebook: for (k, chunk) write valid (in_idx, out_m)
// pairs contiguously + count.  grid: (CHUNKS, 27), block 256.
// ---------------------------------------------------------------------------
__global__ void build_rules_kernel(const int* __restrict__ coords) {
    __shared__ int s_cnt;
    const int tid  = threadIdx.x;
    const int lane = tid & 31;
    const int k    = blockIdx.y;
    const int base = blockIdx.x * CHUNK;

    if (tid == 0) s_cnt = 0;
    __syncthreads();

    const int dx = k / 9 - 1;
    const int dy = (k / 3) % 3 - 1;
    const int dz = k % 3 - 1;
    int2* pout = g_pairs + (k * CHUNKS + blockIdx.x) * CHUNK;

    #pragma unroll
    for (int it = 0; it < CHUNK / 256; ++it) {
        const int m = base + it * 256 + tid;
        int idx = -1;
        if (m < MTOT) {
            const int b  = (m >= NPTS) ? 1 : 0;
            const int nx = coords[3 * m + 0] + dx;
            const int ny = coords[3 * m + 1] + dy;
            const int nz = coords[3 * m + 2] + dz;
            if ((unsigned)nx < SDIM && (unsigned)ny < SDIM && (unsigned)nz < SDIM)
                idx = __ldg(g_grid + ((b * SDIM + nx) * SDIM + ny) * SDIM + nz);
        }
        unsigned bal = __ballot_sync(0xffffffffu, idx >= 0);
        int cnt = __popc(bal);
        int bpos = 0;
        if (lane == 0 && cnt) bpos = atomicAdd(&s_cnt, cnt);
        bpos = __shfl_sync(0xffffffffu, bpos, 0);
        if (idx >= 0) {
            int r = __popc(bal & ((1u << lane) - 1));
            pout[bpos + r] = make_int2(idx, m);
        }
    }
    __syncthreads();
    if (tid == 0) g_cnt[k * CHUNKS + blockIdx.x] = s_cnt;
}

// ---------------------------------------------------------------------------
// gather-GEMM-scatter for one layer.
// grid: (CHUNKS, 27). Block 256 = 8 warps. Per warp-iteration (32 pairs):
//   COOPERATIVE COALESCED GATHER: 8 x (shfl row + LDG.128 spanning 4 whole
//     feature rows + STS.128) into the warp's 32x36 smem tile (aligned,
//     bank-clean per quarter-warp phase).
//   Thread p streams its pair-row via 8 conflict-free LDS.128 (4 cins each),
//   FMAs against W rows broadcast from smem (LDS.128), 32 couts as 16
//   packed f32x2. Results stored pair-major via 16 STS.64; scatter reads
//   tp[j*36 + lane] (conflict-free) -> row-coalesced atomicAdd.
// ---------------------------------------------------------------------------
__global__ __launch_bounds__(GTHREADS)
void spconv_gemm_kernel(const float* __restrict__ in,
                        float*       __restrict__ out,
                        const float* __restrict__ W,
                        int relu_in)
{
    __shared__ __align__(16) float s_W[CDIM * CDIM];          // 4 KB
    __shared__ __align__(16) float s_tr[GWARPS][32 * TSTRIDE];// 36.9 KB

    const int k = blockIdx.y;
    const int c = blockIdx.x;
    const int V = __ldg(g_cnt + k * CHUNKS + c);
    if (V == 0) return;

    const int tid  = threadIdx.x;
    const int lane = tid & 31;
    const int wid  = tid >> 5;

    for (int i = tid; i < CDIM * CDIM; i += GTHREADS)
        s_W[i] = W[k * (CDIM * CDIM) + i];
    __syncthreads();

    const int2* pairs = g_pairs + (k * CHUNKS + c) * CHUNK;
    const int r = lane >> 3;                     // row-in-group 0..3
    const int q = lane & 7;                      // float4 index 0..7

    for (int g0 = wid * 32; g0 < V; g0 += GWARPS * 32) {
        const int p = g0 + lane;
        const int2 pr = (p < V) ? __ldg(pairs + p) : make_int2(0, 0);
        float* tp = s_tr[wid];

        // --- cooperative coalesced gather: 32 rows x 128B ---
        #pragma unroll
        for (int i = 0; i < 8; i++) {
            const int row = 4 * i + r;                       // 0..31
            const int src = __shfl_sync(0xffffffffu, pr.x, row);
            float4 v = __ldg(reinterpret_cast<const float4*>(
                                 in + src * CDIM) + q);
            if (relu_in) {
                v.x = fmaxf(v.x, 0.f); v.y = fmaxf(v.y, 0.f);
                v.z = fmaxf(v.z, 0.f); v.w = fmaxf(v.w, 0.f);
            }
            *reinterpret_cast<float4*>(tp + row * TSTRIDE + 4 * q) = v;
        }
        __syncwarp();

        // --- GEMM: stream own row, 4 cins per LDS.128 ---
        ull acc[16];
        #pragma unroll
        for (int i = 0; i < 16; i++) acc[i] = 0ull;

        #pragma unroll
        for (int c4 = 0; c4 < 8; c4++) {
            const float4 f4 = *reinterpret_cast<const float4*>(
                                  tp + lane * TSTRIDE + 4 * c4);
            const float fv[4] = {f4.x, f4.y, f4.z, f4.w};
            #pragma unroll
            for (int jj = 0; jj < 4; jj++) {
                const int cin = 4 * c4 + jj;
                const ull fb = pack2(fv[jj], fv[jj]);
                const ulonglong2* wr =
                    reinterpret_cast<const ulonglong2*>(s_W + cin * CDIM);
                #pragma unroll
                for (int t = 0; t < 8; t++) {
                    ulonglong2 wq = wr[t];               // LDS.128 broadcast
                    ffma2(acc[2 * t + 0], fb, wq.x);
                    ffma2(acc[2 * t + 1], fb, wq.y);
                }
            }
        }
        __syncwarp();

        // --- store results pair-major (STS.64), overwrite tile ---
        #pragma unroll
        for (int i = 0; i < 16; i++) {
            *reinterpret_cast<ull*>(tp + lane * TSTRIDE + 2 * i) = acc[i];
        }
        __syncwarp();

        // --- scatter: lanes = couts of one pair row, coalesced atomics ---
        const int nv = min(32, V - g0);
        for (int j = 0; j < nv; j++) {
            const int mo = __shfl_sync(0xffffffffu, pr.y, j);
            atomicAdd(out + mo * CDIM + lane, tp[j * TSTRIDE + lane]);
        }
        __syncwarp();
    }
}

// ---------------------------------------------------------------------------
// launch.  Positions: init_zero(1), scatter(2), build_rules(3),
// gemm1(4), gemm2(5), gemm3(6)  ->  ncu lands on a gemm either way.
// ---------------------------------------------------------------------------
extern "C" void kernel_launch(void* const* d_in, const int* in_sizes, int n_in,
                              void* d_out, int out_size)
{
    const float* features = nullptr;
    const int*   coords   = nullptr;
    const float* Ws[3]    = {nullptr, nullptr, nullptr};
    int wcount = 0;

    for (int i = 0; i < n_in; ++i) {
        if (in_sizes[i] == MTOT * CDIM && features == nullptr) {
            features = (const float*)d_in[i];
        } else if (in_sizes[i] == MTOT * 3 && coords == nullptr) {
            coords = (const int*)d_in[i];
        } else if (in_sizes[i] == 27 * CDIM * CDIM && wcount < 3) {
            Ws[wcount++] = (const float*)d_in[i];
        }
    }

    float* x1 = nullptr;
    float* x2 = nullptr;
    cudaGetSymbolAddress((void**)&x1, g_x1);
    cudaGetSymbolAddress((void**)&x2, g_x2);
    float* out = (float*)d_out;

    // 1) fused grid-init + zero of all accumulation buffers
    {
        const int n = MTOT * CDIM / 4;    // > GRID_CELLS/4
        init_zero_kernel<<<(n + 255) / 256, 256>>>(x1, x2, out);
    }
    // 2) scatter
    scatter_kernel<<<(MTOT + 255) / 256, 256>>>(coords);
    // 3) compacted rulebook (shared by all 3 layers)
    {
        dim3 g(CHUNKS, 27);
        build_rules_kernel<<<g, 256>>>(coords);
    }
    // 4-6) three layers of gather-GEMM-scatter
    {
        dim3 g(CHUNKS, 27);
        spconv_gemm_kernel<<<g, GTHREADS>>>(features, x1, Ws[0], 0);
        spconv_gemm_kernel<<<g, GTHREADS>>>(x1,       x2, Ws[1], 1);
        spconv_gemm_kernel<<<g, GTHREADS>>>(x2,      out, Ws[2], 1);
    }
}

// round 10
// speedup vs baseline: 1.6982x; 1.0583x over previous
#include <cuda_runtime.h>
#include <cuda_bf16.h>
#include <cstdint>

// Problem constants (fixed by the dataset): B=2, N=250000, C=32, S=128
#define NPTS   250000
#define NBATCH 2
#define MTOT   (NPTS * NBATCH)        // 500000
#define CDIM   32
#define SDIM   128
#define GRID_CELLS (NBATCH * SDIM * SDIM * SDIM)  // 4,194,304

#define CHUNK    4096                 // output points per rulebook chunk
#define CHUNKS   ((MTOT + CHUNK - 1) / CHUNK)     // 123
#define GTHREADS 128                  // gemm block: 4 warps
#define GWARPS   (GTHREADS / 32)
#define TSTRIDE  36                   // tile row stride (mult of 4: 16B align)

// Scratch (no cudaMalloc allowed)
__device__ int   g_grid[GRID_CELLS];
__device__ int   g_cnt[27 * CHUNKS];              // valid pairs per (k,chunk)
__device__ int2  g_pairs[27 * CHUNKS * CHUNK];    // compacted (in_idx, out_m)
__device__ float g_x1[MTOT * CDIM];
__device__ float g_x2[MTOT * CDIM];

typedef unsigned long long ull;

// ---------------------------------------------------------------------------
// packed f32x2 helpers (dual-rate fp32)
// ---------------------------------------------------------------------------
__device__ __forceinline__ ull pack2(float lo, float hi) {
    ull r;
    asm("mov.b64 %0, {%1, %2};" : "=l"(r) : "f"(lo), "f"(hi));
    return r;
}
__device__ __forceinline__ void ffma2(ull& d, ull a, ull b) {
    asm("fma.rn.f32x2 %0, %1, %2, %0;" : "+l"(d) : "l"(a), "l"(b));
}

// ---------------------------------------------------------------------------
// fused prepass: grid init to -1 + zero all three accumulation buffers
// ---------------------------------------------------------------------------
__global__ void init_zero_kernel(float* __restrict__ a,
                                 float* __restrict__ b,
                                 float* __restrict__ c) {
    int i = blockIdx.x * blockDim.x + threadIdx.x;
    if (i < GRID_CELLS / 4)
        reinterpret_cast<int4*>(g_grid)[i] = make_int4(-1, -1, -1, -1);
    const int n4 = MTOT * CDIM / 4;
    const float4 z = make_float4(0.f, 0.f, 0.f, 0.f);
    if (i < n4) {
        reinterpret_cast<float4*>(a)[i] = z;
        reinterpret_cast<float4*>(b)[i] = z;
        reinterpret_cast<float4*>(c)[i] = z;
    }
}

// ---------------------------------------------------------------------------
// scatter point index into grid
// ---------------------------------------------------------------------------
__global__ void scatter_kernel(const int* __restrict__ coords) {
    int m = blockIdx.x * blockDim.x + threadIdx.x;
    if (m >= MTOT) return;
    int b = (m >= NPTS) ? 1 : 0;
    int x = coords[3 * m + 0];
    int y = coords[3 * m + 1];
    int z = coords[3 * m + 2];
    g_grid[((b * SDIM + x) * SDIM + y) * SDIM + z] = m;
}

// ---------------------------------------------------------------------------
// build compacted rulebook: for (k, chunk) write valid (in_idx, out_m)
// pairs contiguously + count.  grid: (CHUNKS, 27), block 256.
// ---------------------------------------------------------------------------
__global__ void build_rules_kernel(const int* __restrict__ coords) {
    __shared__ int s_cnt;
    const int tid  = threadIdx.x;
    const int lane = tid & 31;
    const int k    = blockIdx.y;
    const int base = blockIdx.x * CHUNK;

    if (tid == 0) s_cnt = 0;
    __syncthreads();

    const int dx = k / 9 - 1;
    const int dy = (k / 3) % 3 - 1;
    const int dz = k % 3 - 1;
    int2* pout = g_pairs + ((long long)k * CHUNKS + blockIdx.x) * CHUNK;

    #pragma unroll
    for (int it = 0; it < CHUNK / 256; ++it) {
        const int m = base + it * 256 + tid;
        int idx = -1;
        if (m < MTOT) {
            const int b  = (m >= NPTS) ? 1 : 0;
            const int nx = coords[3 * m + 0] + dx;
            const int ny = coords[3 * m + 1] + dy;
            const int nz = coords[3 * m + 2] + dz;
            if ((unsigned)nx < SDIM && (unsigned)ny < SDIM && (unsigned)nz < SDIM)
                idx = __ldg(g_grid + ((b * SDIM + nx) * SDIM + ny) * SDIM + nz);
        }
        unsigned bal = __ballot_sync(0xffffffffu, idx >= 0);
        int cnt = __popc(bal);
        int bpos = 0;
        if (lane == 0 && cnt) bpos = atomicAdd(&s_cnt, cnt);
        bpos = __shfl_sync(0xffffffffu, bpos, 0);
        if (idx >= 0) {
            int r = __popc(bal & ((1u << lane) - 1));
            pout[bpos + r] = make_int2(idx, m);
        }
    }
    __syncthreads();
    if (tid == 0) g_cnt[k * CHUNKS + blockIdx.x] = s_cnt;
}

// ---------------------------------------------------------------------------
// gather-GEMM-scatter for one layer.
// grid: (CHUNKS, 27). Block 128 = 4 warps. Per warp-iteration (32 pairs):
//   cooperative coalesced gather (8x LDG.128 spanning 4 whole feature rows
//   + STS.128) into the warp's 32x36 smem tile; threads stream their
//   pair-row via conflict-free LDS.128, FMA against W rows broadcast from
//   smem, 32 couts as 16 packed f32x2; results stored pair-major (STS.64),
//   conflict-free scatter read -> row-coalesced atomicAdd.
// CHUNK=4096 so a non-center block runs ~490 pairs: W staging amortized,
// all warps active for ~4 iterations.
// ---------------------------------------------------------------------------
__global__ __launch_bounds__(GTHREADS)
void spconv_gemm_kernel(const float* __restrict__ in,
                        float*       __restrict__ out,
                        const float* __restrict__ W,
                        int relu_in)
{
    __shared__ __align__(16) float s_W[CDIM * CDIM];          // 4 KB
    __shared__ __align__(16) float s_tr[GWARPS][32 * TSTRIDE];// 18.4 KB

    const int k = blockIdx.y;
    const int c = blockIdx.x;
    const int V = __ldg(g_cnt + k * CHUNKS + c);
    if (V == 0) return;

    const int tid  = threadIdx.x;
    const int lane = tid & 31;
    const int wid  = tid >> 5;

    for (int i = tid; i < CDIM * CDIM; i += GTHREADS)
        s_W[i] = W[k * (CDIM * CDIM) + i];
    __syncthreads();

    const int2* pairs = g_pairs + ((long long)k * CHUNKS + c) * CHUNK;
    const int r = lane >> 3;                     // row-in-group 0..3
    const int q = lane & 7;                      // float4 index 0..7

    for (int g0 = wid * 32; g0 < V; g0 += GWARPS * 32) {
        const int p = g0 + lane;
        const int2 pr = (p < V) ? __ldg(pairs + p) : make_int2(0, 0);
        float* tp = s_tr[wid];

        // --- cooperative coalesced gather: 32 rows x 128B ---
        #pragma unroll
        for (int i = 0; i < 8; i++) {
            const int row = 4 * i + r;                       // 0..31
            const int src = __shfl_sync(0xffffffffu, pr.x, row);
            float4 v = __ldg(reinterpret_cast<const float4*>(
                                 in + src * CDIM) + q);
            if (relu_in) {
                v.x = fmaxf(v.x, 0.f); v.y = fmaxf(v.y, 0.f);
                v.z = fmaxf(v.z, 0.f); v.w = fmaxf(v.w, 0.f);
            }
            *reinterpret_cast<float4*>(tp + row * TSTRIDE + 4 * q) = v;
        }
        __syncwarp();

        // --- GEMM: stream own row, 4 cins per LDS.128 ---
        ull acc[16];
        #pragma unroll
        for (int i = 0; i < 16; i++) acc[i] = 0ull;

        #pragma unroll
        for (int c4 = 0; c4 < 8; c4++) {
            const float4 f4 = *reinterpret_cast<const float4*>(
                                  tp + lane * TSTRIDE + 4 * c4);
            const float fv[4] = {f4.x, f4.y, f4.z, f4.w};
            #pragma unroll
            for (int jj = 0; jj < 4; jj++) {
                const int cin = 4 * c4 + jj;
                const ull fb = pack2(fv[jj], fv[jj]);
                const ulonglong2* wr =
                    reinterpret_cast<const ulonglong2*>(s_W + cin * CDIM);
                #pragma unroll
                for (int t = 0; t < 8; t++) {
                    ulonglong2 wq = wr[t];               // LDS.128 broadcast
                    ffma2(acc[2 * t + 0], fb, wq.x);
                    ffma2(acc[2 * t + 1], fb, wq.y);
                }
            }
        }
        __syncwarp();

        // --- store results pair-major (STS.64), overwrite tile ---
        #pragma unroll
        for (int i = 0; i < 16; i++) {
            *reinterpret_cast<ull*>(tp + lane * TSTRIDE + 2 * i) = acc[i];
        }
        __syncwarp();

        // --- scatter: lanes = couts of one pair row, coalesced atomics ---
        const int nv = min(32, V - g0);
        for (int j = 0; j < nv; j++) {
            const int mo = __shfl_sync(0xffffffffu, pr.y, j);
            atomicAdd(out + mo * CDIM + lane, tp[j * TSTRIDE + lane]);
        }
        __syncwarp();
    }
}

// ---------------------------------------------------------------------------
// launch.  Positions: init_zero(1), scatter(2), build_rules(3),
// gemm1(4), gemm2(5), gemm3(6)  ->  ncu lands on a gemm either way.
// ---------------------------------------------------------------------------
extern "C" void kernel_launch(void* const* d_in, const int* in_sizes, int n_in,
                              void* d_out, int out_size)
{
    const float* features = nullptr;
    const int*   coords   = nullptr;
    const float* Ws[3]    = {nullptr, nullptr, nullptr};
    int wcount = 0;

    for (int i = 0; i < n_in; ++i) {
        if (in_sizes[i] == MTOT * CDIM && features == nullptr) {
            features = (const float*)d_in[i];
        } else if (in_sizes[i] == MTOT * 3 && coords == nullptr) {
            coords = (const int*)d_in[i];
        } else if (in_sizes[i] == 27 * CDIM * CDIM && wcount < 3) {
            Ws[wcount++] = (const float*)d_in[i];
        }
    }

    float* x1 = nullptr;
    float* x2 = nullptr;
    cudaGetSymbolAddress((void**)&x1, g_x1);
    cudaGetSymbolAddress((void**)&x2, g_x2);
    float* out = (float*)d_out;

    // 1) fused grid-init + zero of all accumulation buffers
    {
        const int n = MTOT * CDIM / 4;    // > GRID_CELLS/4
        init_zero_kernel<<<(n + 255) / 256, 256>>>(x1, x2, out);
    }
    // 2) scatter
    scatter_kernel<<<(MTOT + 255) / 256, 256>>>(coords);
    // 3) compacted rulebook (shared by all 3 layers)
    {
        dim3 g(CHUNKS, 27);
        build_rules_kernel<<<g, 256>>>(coords);
    }
    // 4-6) three layers of gather-GEMM-scatter
    {
        dim3 g(CHUNKS, 27);
        spconv_gemm_kernel<<<g, GTHREADS>>>(features, x1, Ws[0], 0);
        spconv_gemm_kernel<<<g, GTHREADS>>>(x1,       x2, Ws[1], 1);
        spconv_gemm_kernel<<<g, GTHREADS>>>(x2,      out, Ws[2], 1);
    }
}

// round 11
// speedup vs baseline: 1.8116x; 1.0668x over previous
#include <cuda_runtime.h>
#include <cuda_bf16.h>
#include <cstdint>

// Problem constants (fixed by the dataset): B=2, N=250000, C=32, S=128
#define NPTS   250000
#define NBATCH 2
#define MTOT   (NPTS * NBATCH)        // 500000
#define CDIM   32
#define SDIM   128
#define GRID_CELLS (NBATCH * SDIM * SDIM * SDIM)  // 4,194,304

#define CHUNK    4096                 // output points per rulebook chunk
#define CHUNKS   ((MTOT + CHUNK - 1) / CHUNK)     // 123
#define GTHREADS 128                  // gemm block: 4 warps
#define GWARPS   (GTHREADS / 32)
#define FSTRIDE  36                   // cin-major tile stride (36*4B, 16B-ok)

// Scratch (no cudaMalloc allowed)
__device__ int   g_grid[GRID_CELLS];
__device__ int   g_cnt[27 * CHUNKS];              // valid pairs per (k,chunk)
__device__ int2  g_pairs[27 * CHUNKS * CHUNK];    // compacted (in_idx, out_m)
__device__ float g_x1[MTOT * CDIM];
__device__ float g_x2[MTOT * CDIM];

typedef unsigned long long ull;

// ---------------------------------------------------------------------------
// packed f32x2 helpers (dual-rate fp32) + vector atomic
// ---------------------------------------------------------------------------
__device__ __forceinline__ ull pack2(float lo, float hi) {
    ull r;
    asm("mov.b64 %0, {%1, %2};" : "=l"(r) : "f"(lo), "f"(hi));
    return r;
}
__device__ __forceinline__ void unpack2(ull v, float& lo, float& hi) {
    asm("mov.b64 {%0, %1}, %2;" : "=f"(lo), "=f"(hi) : "l"(v));
}
__device__ __forceinline__ void ffma2(ull& d, ull a, ull b) {
    asm("fma.rn.f32x2 %0, %1, %2, %0;" : "+l"(d) : "l"(a), "l"(b));
}
__device__ __forceinline__ void red_add_v2(float* p, float a, float b) {
    asm volatile("red.global.add.v2.f32 [%0], {%1, %2};"
                 :: "l"(p), "f"(a), "f"(b) : "memory");
}

// ---------------------------------------------------------------------------
// fused prepass: grid init to -1 + zero all three accumulation buffers
// ---------------------------------------------------------------------------
__global__ void init_zero_kernel(float* __restrict__ a,
                                 float* __restrict__ b,
                                 float* __restrict__ c) {
    int i = blockIdx.x * blockDim.x + threadIdx.x;
    if (i < GRID_CELLS / 4)
        reinterpret_cast<int4*>(g_grid)[i] = make_int4(-1, -1, -1, -1);
    const int n4 = MTOT * CDIM / 4;
    const float4 z = make_float4(0.f, 0.f, 0.f, 0.f);
    if (i < n4) {
        reinterpret_cast<float4*>(a)[i] = z;
        reinterpret_cast<float4*>(b)[i] = z;
        reinterpret_cast<float4*>(c)[i] = z;
    }
}

// ---------------------------------------------------------------------------
// scatter point index into grid
// ---------------------------------------------------------------------------
__global__ void scatter_kernel(const int* __restrict__ coords) {
    int m = blockIdx.x * blockDim.x + threadIdx.x;
    if (m >= MTOT) return;
    int b = (m >= NPTS) ? 1 : 0;
    int x = coords[3 * m + 0];
    int y = coords[3 * m + 1];
    int z = coords[3 * m + 2];
    g_grid[((b * SDIM + x) * SDIM + y) * SDIM + z] = m;
}

// ---------------------------------------------------------------------------
// build compacted rulebook: for (k, chunk) write valid (in_idx, out_m)
// pairs contiguously + count.  grid: (CHUNKS, 27), block 256.
// ---------------------------------------------------------------------------
__global__ void build_rules_kernel(const int* __restrict__ coords) {
    __shared__ int s_cnt;
    const int tid  = threadIdx.x;
    const int lane = tid & 31;
    const int k    = blockIdx.y;
    const int base = blockIdx.x * CHUNK;

    if (tid == 0) s_cnt = 0;
    __syncthreads();

    const int dx = k / 9 - 1;
    const int dy = (k / 3) % 3 - 1;
    const int dz = k % 3 - 1;
    int2* pout = g_pairs + ((long long)k * CHUNKS + blockIdx.x) * CHUNK;

    #pragma unroll
    for (int it = 0; it < CHUNK / 256; ++it) {
        const int m = base + it * 256 + tid;
        int idx = -1;
        if (m < MTOT) {
            const int b  = (m >= NPTS) ? 1 : 0;
            const int nx = coords[3 * m + 0] + dx;
            const int ny = coords[3 * m + 1] + dy;
            const int nz = coords[3 * m + 2] + dz;
            if ((unsigned)nx < SDIM && (unsigned)ny < SDIM && (unsigned)nz < SDIM)
                idx = __ldg(g_grid + ((b * SDIM + nx) * SDIM + ny) * SDIM + nz);
        }
        unsigned bal = __ballot_sync(0xffffffffu, idx >= 0);
        int cnt = __popc(bal);
        int bpos = 0;
        if (lane == 0 && cnt) bpos = atomicAdd(&s_cnt, cnt);
        bpos = __shfl_sync(0xffffffffu, bpos, 0);
        if (idx >= 0) {
            int r = __popc(bal & ((1u << lane) - 1));
            pout[bpos + r] = make_int2(idx, m);
        }
    }
    __syncthreads();
    if (tid == 0) g_cnt[k * CHUNKS + blockIdx.x] = s_cnt;
}

// ---------------------------------------------------------------------------
// gather-GEMM-scatter, register-tiled.
// grid: (CHUNKS, 27). Block 128 = 4 warps. Per warp-iteration (32 pairs):
//  GATHER: 8x (shfl row + LDG.128 covering 4 whole feature rows), stored
//    TRANSPOSED into the warp's [cin][pair] smem tile (stride 36) with
//    XOR swizzle col = pair ^ (4*(cin>>2)) -> STS.32 conflict-free.
//  GEMM: thread (pg=lane>>2, cg=lane&3) owns pairs 4pg..+3, couts 8cg..+7.
//    Per cin: 1 LDS.128 (its 4 pairs' f values, swizzled) + 2 LDS.128
//    (its 8 couts of W) + 16 ffma2. All smem reads conflict-free.
//  SCATTER: direct from registers, red.global.add.v2.f32 (8B aligned),
//    predicated per pair. No smem staging, no transpose.
// ---------------------------------------------------------------------------
__global__ __launch_bounds__(GTHREADS)
void spconv_gemm_kernel(const float* __restrict__ in,
                        float*       __restrict__ out,
                        const float* __restrict__ W,
                        int relu_in)
{
    __shared__ __align__(16) float s_W[CDIM * CDIM];            // 4 KB
    __shared__ __align__(16) float s_F[GWARPS][CDIM * FSTRIDE]; // 18 KB

    const int k = blockIdx.y;
    const int c = blockIdx.x;
    const int V = __ldg(g_cnt + k * CHUNKS + c);
    if (V == 0) return;

    const int tid  = threadIdx.x;
    const int lane = tid & 31;
    const int wid  = tid >> 5;

    for (int i = tid; i < CDIM * CDIM; i += GTHREADS)
        s_W[i] = W[k * (CDIM * CDIM) + i];
    __syncthreads();

    const int2* pairs = g_pairs + ((long long)k * CHUNKS + c) * CHUNK;
    const int r  = lane >> 3;                    // gather row-in-group 0..3
    const int q  = lane & 7;                     // gather float4 index 0..7
    const int pg = lane >> 2;                    // pair group 0..7
    const int cg = lane & 3;                     // cout group 0..3

    for (int g0 = wid * 32; g0 < V; g0 += GWARPS * 32) {
        const int p = g0 + lane;
        const int2 pr = (p < V) ? __ldg(pairs + p) : make_int2(0, 0);
        float* tf = s_F[wid];

        // --- gather: coalesced LDG.128, transposed+swizzled STS.32 ---
        #pragma unroll
        for (int i = 0; i < 8; i++) {
            const int row = 4 * i + r;                       // pair 0..31
            const int src = __shfl_sync(0xffffffffu, pr.x, row);
            float4 v = __ldg(reinterpret_cast<const float4*>(
                                 in + src * CDIM) + q);
            if (relu_in) {
                v.x = fmaxf(v.x, 0.f); v.y = fmaxf(v.y, 0.f);
                v.z = fmaxf(v.z, 0.f); v.w = fmaxf(v.w, 0.f);
            }
            const int col = row ^ (4 * q);       // swizzle: cin>>2 == q here
            tf[(4 * q + 0) * FSTRIDE + col] = v.x;
            tf[(4 * q + 1) * FSTRIDE + col] = v.y;
            tf[(4 * q + 2) * FSTRIDE + col] = v.z;
            tf[(4 * q + 3) * FSTRIDE + col] = v.w;
        }
        __syncwarp();

        // --- GEMM: 4 pairs x 8 couts per thread ---
        ull acc[16];
        #pragma unroll
        for (int i = 0; i < 16; i++) acc[i] = 0ull;

        #pragma unroll
        for (int cin = 0; cin < 32; cin++) {
            const int colb = (4 * pg) ^ (4 * (cin >> 2));    // swizzled base
            const float4 f4 = *reinterpret_cast<const float4*>(
                                  tf + cin * FSTRIDE + colb);
            const ulonglong2 w0 = *reinterpret_cast<const ulonglong2*>(
                                      s_W + cin * CDIM + 8 * cg);
            const ulonglong2 w1 = *reinterpret_cast<const ulonglong2*>(
                                      s_W + cin * CDIM + 8 * cg + 4);
            const float fv[4] = {f4.x, f4.y, f4.z, f4.w};
            #pragma unroll
            for (int j = 0; j < 4; j++) {
                const ull fj = pack2(fv[j], fv[j]);
                ffma2(acc[4 * j + 0], fj, w0.x);
                ffma2(acc[4 * j + 1], fj, w0.y);
                ffma2(acc[4 * j + 2], fj, w1.x);
                ffma2(acc[4 * j + 3], fj, w1.y);
            }
        }
        __syncwarp();        // tile reusable next iteration

        // --- scatter: direct vector atomics from registers ---
        #pragma unroll
        for (int j = 0; j < 4; j++) {
            const int pj = 4 * pg + j;
            const int mo = __shfl_sync(0xffffffffu, pr.y, pj);
            if (g0 + pj < V) {
                float* bp = out + mo * CDIM + 8 * cg;
                #pragma unroll
                for (int t = 0; t < 4; t++) {
                    float lo, hi;
                    unpack2(acc[4 * j + t], lo, hi);
                    red_add_v2(bp + 2 * t, lo, hi);
                }
            }
        }
    }
}

// ---------------------------------------------------------------------------
// launch.  Positions: init_zero(1), scatter(2), build_rules(3),
// gemm1(4), gemm2(5), gemm3(6)  ->  ncu lands on a gemm either way.
// ---------------------------------------------------------------------------
extern "C" void kernel_launch(void* const* d_in, const int* in_sizes, int n_in,
                              void* d_out, int out_size)
{
    const float* features = nullptr;
    const int*   coords   = nullptr;
    const float* Ws[3]    = {nullptr, nullptr, nullptr};
    int wcount = 0;

    for (int i = 0; i < n_in; ++i) {
        if (in_sizes[i] == MTOT * CDIM && features == nullptr) {
            features = (const float*)d_in[i];
        } else if (in_sizes[i] == MTOT * 3 && coords == nullptr) {
            coords = (const int*)d_in[i];
        } else if (in_sizes[i] == 27 * CDIM * CDIM && wcount < 3) {
            Ws[wcount++] = (const float*)d_in[i];
        }
    }

    float* x1 = nullptr;
    float* x2 = nullptr;
    cudaGetSymbolAddress((void**)&x1, g_x1);
    cudaGetSymbolAddress((void**)&x2, g_x2);
    float* out = (float*)d_out;

    // 1) fused grid-init + zero of all accumulation buffers
    {
        const int n = MTOT * CDIM / 4;    // > GRID_CELLS/4
        init_zero_kernel<<<(n + 255) / 256, 256>>>(x1, x2, out);
    }
    // 2) scatter
    scatter_kernel<<<(MTOT + 255) / 256, 256>>>(coords);
    // 3) compacted rulebook (shared by all 3 layers)
    {
        dim3 g(CHUNKS, 27);
        build_rules_kernel<<<g, 256>>>(coords);
    }
    // 4-6) three layers of gather-GEMM-scatter
    {
        dim3 g(CHUNKS, 27);
        spconv_gemm_kernel<<<g, GTHREADS>>>(features, x1, Ws[0], 0);
        spconv_gemm_kernel<<<g, GTHREADS>>>(x1,       x2, Ws[1], 1);
        spconv_gemm_kernel<<<g, GTHREADS>>>(x2,      out, Ws[2], 1);
    }
}

// round 12
// speedup vs baseline: 2.1172x; 1.1687x over previous
#include <cuda_runtime.h>
#include <cuda_bf16.h>
#include <cstdint>

// Problem constants (fixed by the dataset): B=2, N=250000, C=32, S=128
#define NPTS   250000
#define NBATCH 2
#define MTOT   (NPTS * NBATCH)        // 500000
#define CDIM   32
#define SDIM   128
#define GRID_CELLS (NBATCH * SDIM * SDIM * SDIM)  // 4,194,304

#define CHUNK    4096                 // output points per rulebook chunk
#define CHUNKS   ((MTOT + CHUNK - 1) / CHUNK)     // 123
#define SEG      1024                 // pairs per gemm block (imbalance fix)
#define SEGS     (CHUNK / SEG)        // 4
#define GTHREADS 128                  // gemm block: 4 warps
#define GWARPS   (GTHREADS / 32)
#define FSTRIDE  36                   // cin-major tile stride

// Scratch (no cudaMalloc allowed)
__device__ int   g_grid[GRID_CELLS];
__device__ int   g_cnt[27 * CHUNKS];              // valid pairs per (k,chunk)
__device__ int2  g_pairs[27 * CHUNKS * CHUNK];    // compacted (in_idx, out_m)
__device__ float g_x1[MTOT * CDIM];
__device__ float g_x2[MTOT * CDIM];

typedef unsigned long long ull;

// ---------------------------------------------------------------------------
// packed f32x2 helpers (dual-rate fp32) + vector atomic
// ---------------------------------------------------------------------------
__device__ __forceinline__ ull pack2(float lo, float hi) {
    ull r;
    asm("mov.b64 %0, {%1, %2};" : "=l"(r) : "f"(lo), "f"(hi));
    return r;
}
__device__ __forceinline__ void unpack2(ull v, float& lo, float& hi) {
    asm("mov.b64 {%0, %1}, %2;" : "=f"(lo), "=f"(hi) : "l"(v));
}
__device__ __forceinline__ void ffma2(ull& d, ull a, ull b) {
    asm("fma.rn.f32x2 %0, %1, %2, %0;" : "+l"(d) : "l"(a), "l"(b));
}
__device__ __forceinline__ void red_add_v2(float* p, float a, float b) {
    asm volatile("red.global.add.v2.f32 [%0], {%1, %2};"
                 :: "l"(p), "f"(a), "f"(b) : "memory");
}

// ---------------------------------------------------------------------------
// fused prepass: grid init to -1 + zero all three accumulation buffers
// ---------------------------------------------------------------------------
__global__ void init_zero_kernel(float* __restrict__ a,
                                 float* __restrict__ b,
                                 float* __restrict__ c) {
    int i = blockIdx.x * blockDim.x + threadIdx.x;
    if (i < GRID_CELLS / 4)
        reinterpret_cast<int4*>(g_grid)[i] = make_int4(-1, -1, -1, -1);
    const int n4 = MTOT * CDIM / 4;
    const float4 z = make_float4(0.f, 0.f, 0.f, 0.f);
    if (i < n4) {
        reinterpret_cast<float4*>(a)[i] = z;
        reinterpret_cast<float4*>(b)[i] = z;
        reinterpret_cast<float4*>(c)[i] = z;
    }
}

// ---------------------------------------------------------------------------
// scatter point index into grid
// ---------------------------------------------------------------------------
__global__ void scatter_kernel(const int* __restrict__ coords) {
    int m = blockIdx.x * blockDim.x + threadIdx.x;
    if (m >= MTOT) return;
    int b = (m >= NPTS) ? 1 : 0;
    int x = coords[3 * m + 0];
    int y = coords[3 * m + 1];
    int z = coords[3 * m + 2];
    g_grid[((b * SDIM + x) * SDIM + y) * SDIM + z] = m;
}

// ---------------------------------------------------------------------------
// build compacted rulebook: for (k, chunk) write valid (in_idx, out_m)
// pairs contiguously + count.  grid: (CHUNKS, 27), block 256.
// ---------------------------------------------------------------------------
__global__ void build_rules_kernel(const int* __restrict__ coords) {
    __shared__ int s_cnt;
    const int tid  = threadIdx.x;
    const int lane = tid & 31;
    const int k    = blockIdx.y;
    const int base = blockIdx.x * CHUNK;

    if (tid == 0) s_cnt = 0;
    __syncthreads();

    const int dx = k / 9 - 1;
    const int dy = (k / 3) % 3 - 1;
    const int dz = k % 3 - 1;
    int2* pout = g_pairs + ((long long)k * CHUNKS + blockIdx.x) * CHUNK;

    #pragma unroll
    for (int it = 0; it < CHUNK / 256; ++it) {
        const int m = base + it * 256 + tid;
        int idx = -1;
        if (m < MTOT) {
            const int b  = (m >= NPTS) ? 1 : 0;
            const int nx = coords[3 * m + 0] + dx;
            const int ny = coords[3 * m + 1] + dy;
            const int nz = coords[3 * m + 2] + dz;
            if ((unsigned)nx < SDIM && (unsigned)ny < SDIM && (unsigned)nz < SDIM)
                idx = __ldg(g_grid + ((b * SDIM + nx) * SDIM + ny) * SDIM + nz);
        }
        unsigned bal = __ballot_sync(0xffffffffu, idx >= 0);
        int cnt = __popc(bal);
        int bpos = 0;
        if (lane == 0 && cnt) bpos = atomicAdd(&s_cnt, cnt);
        bpos = __shfl_sync(0xffffffffu, bpos, 0);
        if (idx >= 0) {
            int r = __popc(bal & ((1u << lane) - 1));
            pout[bpos + r] = make_int2(idx, m);
        }
    }
    __syncthreads();
    if (tid == 0) g_cnt[k * CHUNKS + blockIdx.x] = s_cnt;
}

// ---------------------------------------------------------------------------
// gather-GEMM-scatter, register-tiled + SOFTWARE-PIPELINED.
// grid: (CHUNKS*SEGS, 27). Each block owns a <=SEG-pair window (splits the
// heavy center-offset chunks 4-way). Block 128 = 4 warps.
// Per warp-iteration (32 pairs), pipelined:
//   - fetch NEXT iteration's pairs + 8 coalesced LDG.128 rows into regs
//   - FMA over the CURRENT smem tile (512 ffma2) -- hides the LDG latency
//   - scatter current acc via red.global.add.v2.f32
//   - STS the prefetched rows (transposed + XOR swizzle) into the tile
// Tile is reused in place (all reads precede the STS each iteration).
// ---------------------------------------------------------------------------
__global__ __launch_bounds__(GTHREADS)
void spconv_gemm_kernel(const float* __restrict__ in,
                        float*       __restrict__ out,
                        const float* __restrict__ W,
                        int relu_in)
{
    __shared__ __align__(16) float s_W[CDIM * CDIM];            // 4 KB
    __shared__ __align__(16) float s_F[GWARPS][CDIM * FSTRIDE]; // 18 KB

    const int k    = blockIdx.y;
    const int c    = blockIdx.x / SEGS;
    const int seg  = blockIdx.x - c * SEGS;
    const int V    = __ldg(g_cnt + k * CHUNKS + c);
    const int lo   = seg * SEG;
    if (lo >= V) return;
    const int hi   = min(V, lo + SEG);

    const int tid  = threadIdx.x;
    const int lane = tid & 31;
    const int wid  = tid >> 5;

    for (int i = tid; i < CDIM * CDIM; i += GTHREADS)
        s_W[i] = W[k * (CDIM * CDIM) + i];
    __syncthreads();

    const int2* pairs = g_pairs + ((long long)k * CHUNKS + c) * CHUNK;
    const int r  = lane >> 3;                    // gather row-in-group 0..3
    const int q  = lane & 7;                     // gather float4 index 0..7
    const int pg = lane >> 2;                    // pair group 0..7
    const int cg = lane & 3;                     // cout group 0..3

    int g0 = lo + wid * 32;
    if (g0 >= hi) return;
    float* tf = s_F[wid];

    // ---- prologue: fetch + stage first tile ----
    int2 pr = (g0 + lane < hi) ? __ldg(pairs + g0 + lane) : make_int2(0, 0);
    {
        float4 vbuf[8];
        #pragma unroll
        for (int i = 0; i < 8; i++) {
            const int row = 4 * i + r;
            const int src = __shfl_sync(0xffffffffu, pr.x, row);
            float4 v = __ldg(reinterpret_cast<const float4*>(in + src * CDIM) + q);
            if (relu_in) {
                v.x = fmaxf(v.x, 0.f); v.y = fmaxf(v.y, 0.f);
                v.z = fmaxf(v.z, 0.f); v.w = fmaxf(v.w, 0.f);
            }
            vbuf[i] = v;
        }
        #pragma unroll
        for (int i = 0; i < 8; i++) {
            const int row = 4 * i + r;
            const int col = row ^ (4 * q);
            tf[(4 * q + 0) * FSTRIDE + col] = vbuf[i].x;
            tf[(4 * q + 1) * FSTRIDE + col] = vbuf[i].y;
            tf[(4 * q + 2) * FSTRIDE + col] = vbuf[i].z;
            tf[(4 * q + 3) * FSTRIDE + col] = vbuf[i].w;
        }
    }
    __syncwarp();

    for (; g0 < hi; ) {
        const int g1 = g0 + GWARPS * 32;
        const bool more = (g1 < hi);

        // ---- prefetch next tile into registers (latency hidden by FMAs) ----
        int2 pr_next = make_int2(0, 0);
        float4 vbuf[8];
        if (more) {
            pr_next = (g1 + lane < hi) ? __ldg(pairs + g1 + lane)
                                       : make_int2(0, 0);
            #pragma unroll
            for (int i = 0; i < 8; i++) {
                const int row = 4 * i + r;
                const int src = __shfl_sync(0xffffffffu, pr_next.x, row);
                float4 v = __ldg(reinterpret_cast<const float4*>(
                                     in + src * CDIM) + q);
                if (relu_in) {
                    v.x = fmaxf(v.x, 0.f); v.y = fmaxf(v.y, 0.f);
                    v.z = fmaxf(v.z, 0.f); v.w = fmaxf(v.w, 0.f);
                }
                vbuf[i] = v;
            }
        }

        // ---- GEMM over current tile: 4 pairs x 8 couts per thread ----
        ull acc[16];
        #pragma unroll
        for (int i = 0; i < 16; i++) acc[i] = 0ull;

        #pragma unroll
        for (int cin = 0; cin < 32; cin++) {
            const int colb = (4 * pg) ^ (4 * (cin >> 2));
            const float4 f4 = *reinterpret_cast<const float4*>(
                                  tf + cin * FSTRIDE + colb);
            const ulonglong2 w0 = *reinterpret_cast<const ulonglong2*>(
                                      s_W + cin * CDIM + 8 * cg);
            const ulonglong2 w1 = *reinterpret_cast<const ulonglong2*>(
                                      s_W + cin * CDIM + 8 * cg + 4);
            const float fv[4] = {f4.x, f4.y, f4.z, f4.w};
            #pragma unroll
            for (int j = 0; j < 4; j++) {
                const ull fj = pack2(fv[j], fv[j]);
                ffma2(acc[4 * j + 0], fj, w0.x);
                ffma2(acc[4 * j + 1], fj, w0.y);
                ffma2(acc[4 * j + 2], fj, w1.x);
                ffma2(acc[4 * j + 3], fj, w1.y);
            }
        }

        // ---- scatter current results: vector atomics from registers ----
        #pragma unroll
        for (int j = 0; j < 4; j++) {
            const int pj = 4 * pg + j;
            const int mo = __shfl_sync(0xffffffffu, pr.y, pj);
            if (g0 + pj < hi) {
                float* bp = out + mo * CDIM + 8 * cg;
                #pragma unroll
                for (int t = 0; t < 4; t++) {
                    float lo2, hi2;
                    unpack2(acc[4 * j + t], lo2, hi2);
                    red_add_v2(bp + 2 * t, lo2, hi2);
                }
            }
        }
        __syncwarp();                     // all reads of tile done

        // ---- stage prefetched tile in place ----
        if (more) {
            #pragma unroll
            for (int i = 0; i < 8; i++) {
                const int row = 4 * i + r;
                const int col = row ^ (4 * q);
                tf[(4 * q + 0) * FSTRIDE + col] = vbuf[i].x;
                tf[(4 * q + 1) * FSTRIDE + col] = vbuf[i].y;
                tf[(4 * q + 2) * FSTRIDE + col] = vbuf[i].z;
                tf[(4 * q + 3) * FSTRIDE + col] = vbuf[i].w;
            }
        }
        __syncwarp();

        pr = pr_next;
        g0 = g1;
    }
}

// ---------------------------------------------------------------------------
// launch.  Positions: init_zero(1), scatter(2), build_rules(3),
// gemm1(4), gemm2(5), gemm3(6)  ->  ncu lands on a gemm either way.
// ---------------------------------------------------------------------------
extern "C" void kernel_launch(void* const* d_in, const int* in_sizes, int n_in,
                              void* d_out, int out_size)
{
    const float* features = nullptr;
    const int*   coords   = nullptr;
    const float* Ws[3]    = {nullptr, nullptr, nullptr};
    int wcount = 0;

    for (int i = 0; i < n_in; ++i) {
        if (in_sizes[i] == MTOT * CDIM && features == nullptr) {
            features = (const float*)d_in[i];
        } else if (in_sizes[i] == MTOT * 3 && coords == nullptr) {
            coords = (const int*)d_in[i];
        } else if (in_sizes[i] == 27 * CDIM * CDIM && wcount < 3) {
            Ws[wcount++] = (const float*)d_in[i];
        }
    }

    float* x1 = nullptr;
    float* x2 = nullptr;
    cudaGetSymbolAddress((void**)&x1, g_x1);
    cudaGetSymbolAddress((void**)&x2, g_x2);
    float* out = (float*)d_out;

    // 1) fused grid-init + zero of all accumulation buffers
    {
        const int n = MTOT * CDIM / 4;    // > GRID_CELLS/4
        init_zero_kernel<<<(n + 255) / 256, 256>>>(x1, x2, out);
    }
    // 2) scatter
    scatter_kernel<<<(MTOT + 255) / 256, 256>>>(coords);
    // 3) compacted rulebook (shared by all 3 layers)
    {
        dim3 g(CHUNKS, 27);
        build_rules_kernel<<<g, 256>>>(coords);
    }
    // 4-6) three layers of gather-GEMM-scatter (segmented grid)
    {
        dim3 g(CHUNKS * SEGS, 27);
        spconv_gemm_kernel<<<g, GTHREADS>>>(features, x1, Ws[0], 0);
        spconv_gemm_kernel<<<g, GTHREADS>>>(x1,       x2, Ws[1], 1);
        spconv_gemm_kernel<<<g, GTHREADS>>>(x2,      out, Ws[2], 1);
    }
}